// round 2
// baseline (speedup 1.0000x reference)
#include <cuda_runtime.h>
#include <cstdint>

// ---------------------------------------------------------------------------
// GraphSAGE 3-layer, tf32 mma.sync GEMMs + CSR gather mean-aggregation.
// Key identity: meanAgg(H) @ W == meanAgg(H @ W)  (aggregate the narrower one)
// ---------------------------------------------------------------------------

#define N_NODES_MAX 50000
#define N_EDGES_MAX 400000

// Static scratch (allocation-free rule: __device__ globals)
__device__ float g_P[(size_t)N_NODES_MAX * 2048];
__device__ float g_Q[(size_t)N_NODES_MAX * 2048];
__device__ float g_R[(size_t)N_NODES_MAX * 2048];
__device__ float g_AGGX[(size_t)N_NODES_MAX * 128];
__device__ int   g_cnt[N_NODES_MAX];
__device__ int   g_rowptr[N_NODES_MAX + 1];
__device__ int   g_cursor[N_NODES_MAX];
__device__ int   g_colsrc[N_EDGES_MAX];
__device__ float g_invdeg[N_NODES_MAX];
__device__ int   g_is64;

// ---------------------------------------------------------------------------
// Edge-index dtype autodetect: int64 values < 2^31 have zero high words.
// ---------------------------------------------------------------------------
__global__ void detect_kernel(const int* __restrict__ ei_w) {
    // single thread: check first 256 odd words
    int allz = 1;
    for (int i = 1; i < 512; i += 2)
        if (ei_w[i] != 0) { allz = 0; break; }
    g_is64 = allz;
}

__device__ __forceinline__ int load_idx(const void* ei, size_t pos, int is64) {
    if (is64) return (int)((const long long*)ei)[pos];
    return ((const int*)ei)[pos];
}

// ---------------------------------------------------------------------------
// CSR build
// ---------------------------------------------------------------------------
__global__ void zero_int_kernel(int* p, int n) {
    int i = blockIdx.x * blockDim.x + threadIdx.x;
    if (i < n) p[i] = 0;
}

__global__ void count_kernel(const void* __restrict__ ei, int* __restrict__ cnt,
                             int E, int N) {
    int e = blockIdx.x * blockDim.x + threadIdx.x;
    if (e < E) {
        int d = load_idx(ei, (size_t)E + e, g_is64);
        if (d >= 0 && d < N) atomicAdd(&cnt[d], 1);
    }
}

// single-block exclusive scan over N counts -> rowptr[N+1]
__global__ void scan_kernel(const int* __restrict__ cnt, int* __restrict__ rowptr, int N) {
    __shared__ int sm[1024];
    __shared__ int s_carry;
    int tid = threadIdx.x;
    if (tid == 0) s_carry = 0;
    __syncthreads();
    for (int base = 0; base < N; base += 1024) {
        int v = (base + tid < N) ? cnt[base + tid] : 0;
        sm[tid] = v;
        __syncthreads();
        for (int off = 1; off < 1024; off <<= 1) {
            int t = (tid >= off) ? sm[tid - off] : 0;
            __syncthreads();
            sm[tid] += t;
            __syncthreads();
        }
        if (base + tid < N) rowptr[base + tid] = s_carry + sm[tid] - v;
        int total = sm[1023];
        __syncthreads();
        if (tid == 0) s_carry += total;
        __syncthreads();
    }
    if (threadIdx.x == 0) rowptr[N] = s_carry;
}

__global__ void prep_kernel(const int* __restrict__ cnt, const int* __restrict__ rowptr,
                            float* __restrict__ invdeg, int* __restrict__ cursor, int N) {
    int i = blockIdx.x * blockDim.x + threadIdx.x;
    if (i < N) {
        cursor[i] = rowptr[i];
        int c = cnt[i];
        invdeg[i] = 1.0f / (float)(c > 0 ? c : 1);
    }
}

__global__ void fill_kernel(const void* __restrict__ ei, int* __restrict__ cursor,
                            int* __restrict__ colsrc, int E, int N) {
    int e = blockIdx.x * blockDim.x + threadIdx.x;
    if (e < E) {
        int is64 = g_is64;
        int d = load_idx(ei, (size_t)E + e, is64);
        int s = load_idx(ei, (size_t)e, is64);
        if (d >= 0 && d < N && s >= 0 && s < N) {
            int p = atomicAdd(&cursor[d], 1);
            if (p < E) colsrc[p] = s;
        }
    }
}

// ---------------------------------------------------------------------------
// Mean aggregation: out[n] = invdeg[n] * sum_{j in row n} X[colsrc[j]]
// D compile-time; 128 threads, float4-vectorized gather (rows contiguous).
// ---------------------------------------------------------------------------
template <int D>
__global__ void agg_mean_kernel(const float* __restrict__ X,
                                const int* __restrict__ rowptr,
                                const int* __restrict__ colsrc,
                                const float* __restrict__ invdeg,
                                float* __restrict__ out) {
    constexpr int NF4 = D / 4;
    constexpr int TPB = 128;
    constexpr int PT = (NF4 + TPB - 1) / TPB;
    int n = blockIdx.x;
    int tid = threadIdx.x;

    float4 acc[PT];
#pragma unroll
    for (int k = 0; k < PT; k++) acc[k] = make_float4(0.f, 0.f, 0.f, 0.f);

    int s = rowptr[n], e = rowptr[n + 1];
    for (int j = s; j < e; j++) {
        const float4* row = (const float4*)(X + (size_t)colsrc[j] * D);
#pragma unroll
        for (int k = 0; k < PT; k++) {
            int c = tid + k * TPB;
            if (NF4 % TPB == 0 || c < NF4) {
                float4 v = row[c];
                acc[k].x += v.x; acc[k].y += v.y; acc[k].z += v.z; acc[k].w += v.w;
            }
        }
    }
    float sc = invdeg[n];
    float4* orow = (float4*)(out + (size_t)n * D);
#pragma unroll
    for (int k = 0; k < PT; k++) {
        int c = tid + k * TPB;
        if (NF4 % TPB == 0 || c < NF4) {
            float4 a = acc[k];
            a.x *= sc; a.y *= sc; a.z *= sc; a.w *= sc;
            orow[c] = a;
        }
    }
}

// ---------------------------------------------------------------------------
// TF32 GEMM via mma.sync.m16n8k8 (row.col).
// C[M,Nout] = epilogue( A1@W1 (+ A2@W2) (+ Cin) (+ bias) ), optional relu.
// Block tile 128x128x32, 256 threads = 8 warps (2x4), warp tile 64x32.
// ---------------------------------------------------------------------------
__device__ __forceinline__ uint32_t f2tf(float x) {
    uint32_t r;
    asm("cvt.rna.tf32.f32 %0, %1;" : "=r"(r) : "f"(x));
    return r;
}

#define BM 128
#define BN 128
#define BKK 32
#define ASTRIDE 36   // padded to keep frag loads conflict-light
#define WSTRIDE 136

__global__ __launch_bounds__(256) void gemm_tf32_kernel(
    const float* __restrict__ A1, const float* __restrict__ W1,
    const float* __restrict__ A2, const float* __restrict__ W2,
    const float* __restrict__ Cin, const float* __restrict__ bias,
    float* __restrict__ C, int M, int Nout, int K, int do_relu) {
    __shared__ uint32_t As[BM * ASTRIDE];
    __shared__ uint32_t Ws[BKK * WSTRIDE];

    int tid = threadIdx.x;
    int bm = blockIdx.y * BM, bn = blockIdx.x * BN;
    int warp = tid >> 5, lane = tid & 31;
    int g = lane >> 2, tg = lane & 3;
    int wm = (warp >> 2) * 64, wn = (warp & 3) * 32;

    float acc[4][4][4];
#pragma unroll
    for (int i = 0; i < 4; i++)
#pragma unroll
        for (int j = 0; j < 4; j++)
#pragma unroll
            for (int k = 0; k < 4; k++) acc[i][j][k] = 0.f;

    int npass = (A2 != nullptr) ? 2 : 1;
    for (int pass = 0; pass < npass; ++pass) {
        const float* Ap = pass ? A2 : A1;
        const float* Wp = pass ? W2 : W1;
        for (int kt = 0; kt < K; kt += BKK) {
            // load A tile [128 x 32]
#pragma unroll
            for (int i = 0; i < 4; i++) {
                int idx = tid + i * 256;
                int r = idx >> 3;
                int c4 = idx & 7;
                int gm = bm + r;
                float4 v;
                if (gm < M) v = *(const float4*)(Ap + (size_t)gm * K + kt + c4 * 4);
                else v = make_float4(0.f, 0.f, 0.f, 0.f);
                uint32_t* dst = &As[r * ASTRIDE + c4 * 4];
                dst[0] = f2tf(v.x); dst[1] = f2tf(v.y);
                dst[2] = f2tf(v.z); dst[3] = f2tf(v.w);
            }
            // load W tile [32 x 128]
#pragma unroll
            for (int i = 0; i < 4; i++) {
                int idx = tid + i * 256;
                int r = idx >> 5;
                int c4 = idx & 31;
                float4 v = *(const float4*)(Wp + (size_t)(kt + r) * Nout + bn + c4 * 4);
                uint32_t* dst = &Ws[r * WSTRIDE + c4 * 4];
                dst[0] = f2tf(v.x); dst[1] = f2tf(v.y);
                dst[2] = f2tf(v.z); dst[3] = f2tf(v.w);
            }
            __syncthreads();
#pragma unroll
            for (int ks = 0; ks < BKK; ks += 8) {
                uint32_t a[4][4], b[4][2];
#pragma unroll
                for (int im = 0; im < 4; im++) {
                    int row = wm + 16 * im + g;
                    const uint32_t* p = &As[row * ASTRIDE + ks];
                    a[im][0] = p[tg];
                    a[im][1] = p[8 * ASTRIDE + tg];
                    a[im][2] = p[tg + 4];
                    a[im][3] = p[8 * ASTRIDE + tg + 4];
                }
#pragma unroll
                for (int in = 0; in < 4; in++) {
                    int col = wn + 8 * in + g;
                    b[in][0] = Ws[(ks + tg) * WSTRIDE + col];
                    b[in][1] = Ws[(ks + tg + 4) * WSTRIDE + col];
                }
#pragma unroll
                for (int im = 0; im < 4; im++)
#pragma unroll
                    for (int in = 0; in < 4; in++) {
                        asm volatile(
                            "mma.sync.aligned.m16n8k8.row.col.f32.tf32.tf32.f32 "
                            "{%0,%1,%2,%3}, {%4,%5,%6,%7}, {%8,%9}, {%0,%1,%2,%3};"
                            : "+f"(acc[im][in][0]), "+f"(acc[im][in][1]),
                              "+f"(acc[im][in][2]), "+f"(acc[im][in][3])
                            : "r"(a[im][0]), "r"(a[im][1]), "r"(a[im][2]), "r"(a[im][3]),
                              "r"(b[in][0]), "r"(b[in][1]));
                    }
            }
            __syncthreads();
        }
    }

    // epilogue
#pragma unroll
    for (int im = 0; im < 4; im++) {
        int row = wm + 16 * im + g;
#pragma unroll
        for (int half = 0; half < 2; half++) {
            int gm = bm + row + half * 8;
            if (gm >= M) continue;
#pragma unroll
            for (int in = 0; in < 4; in++) {
                int gcol = bn + wn + 8 * in + 2 * tg;
#pragma unroll
                for (int j = 0; j < 2; j++) {
                    float v = acc[im][in][half * 2 + j];
                    size_t idx = (size_t)gm * Nout + gcol + j;
                    if (Cin) v += Cin[idx];
                    if (bias) v += bias[gcol + j];
                    if (do_relu) v = fmaxf(v, 0.f);
                    C[idx] = v;
                }
            }
        }
    }
}

// ---------------------------------------------------------------------------
// Row L2 normalize, D = 1024, in-place capable (block owns its row).
// ---------------------------------------------------------------------------
__global__ void norm_kernel(const float* __restrict__ H, float* __restrict__ out) {
    int n = blockIdx.x, tid = threadIdx.x;  // 256 threads, 256 float4 per row
    const float4* row = (const float4*)(H + (size_t)n * 1024);
    float4 v = row[tid];
    float ss = v.x * v.x + v.y * v.y + v.z * v.z + v.w * v.w;
#pragma unroll
    for (int off = 16; off; off >>= 1) ss += __shfl_xor_sync(0xffffffffu, ss, off);
    __shared__ float red[8];
    __shared__ float s_scale;
    int warp = tid >> 5, lane = tid & 31;
    if (lane == 0) red[warp] = ss;
    __syncthreads();
    if (tid == 0) {
        float t = 0.f;
#pragma unroll
        for (int i = 0; i < 8; i++) t += red[i];
        float nm = sqrtf(t);
        s_scale = 1.0f / fmaxf(nm, 1e-12f);
    }
    __syncthreads();
    float sc = s_scale;
    float4* o = (float4*)(out + (size_t)n * 1024);
    v.x *= sc; v.y *= sc; v.z *= sc; v.w *= sc;
    o[tid] = v;
}

// ---------------------------------------------------------------------------
// Launch
// ---------------------------------------------------------------------------
extern "C" void kernel_launch(void* const* d_in, const int* in_sizes, int n_in,
                              void* d_out, int out_size) {
    const float* x       = (const float*)d_in[0];
    const void*  ei      = (const void*)d_in[2];
    const float* W1l     = (const float*)d_in[3];
    const float* W1r     = (const float*)d_in[4];
    const float* b1      = (const float*)d_in[5];
    const float* W2l     = (const float*)d_in[6];
    const float* W2r     = (const float*)d_in[7];
    const float* b2      = (const float*)d_in[8];
    const float* W3l     = (const float*)d_in[9];
    const float* W3r     = (const float*)d_in[10];
    const float* b3      = (const float*)d_in[11];
    float* out           = (float*)d_out;

    int M = in_sizes[0] / 128;
    int E = in_sizes[2] / 2;

    float *P, *Q, *R, *AGGX, *invdeg;
    int *cnt, *rowptr, *cursor, *colsrc;
    cudaGetSymbolAddress((void**)&P, g_P);
    cudaGetSymbolAddress((void**)&Q, g_Q);
    cudaGetSymbolAddress((void**)&R, g_R);
    cudaGetSymbolAddress((void**)&AGGX, g_AGGX);
    cudaGetSymbolAddress((void**)&cnt, g_cnt);
    cudaGetSymbolAddress((void**)&rowptr, g_rowptr);
    cudaGetSymbolAddress((void**)&cursor, g_cursor);
    cudaGetSymbolAddress((void**)&colsrc, g_colsrc);
    cudaGetSymbolAddress((void**)&invdeg, g_invdeg);

    // dtype autodetect + CSR build
    detect_kernel<<<1, 1>>>((const int*)ei);
    zero_int_kernel<<<(M + 255) / 256, 256>>>(cnt, M);
    count_kernel<<<(E + 255) / 256, 256>>>(ei, cnt, E, M);
    scan_kernel<<<1, 1024>>>(cnt, rowptr, M);
    prep_kernel<<<(M + 255) / 256, 256>>>(cnt, rowptr, invdeg, cursor, M);
    fill_kernel<<<(E + 255) / 256, 256>>>(ei, cursor, colsrc, E, M);

    dim3 gN2((2048 / BN), (M + BM - 1) / BM);
    dim3 gN1((1024 / BN), (M + BM - 1) / BM);

    // Layer 1: h1 = relu( meanAgg(x)@W1l + x@W1r + b1 )   -> P
    agg_mean_kernel<128><<<M, 128>>>(x, rowptr, colsrc, invdeg, AGGX);
    gemm_tf32_kernel<<<gN2, 256>>>(AGGX, W1l, x, W1r, nullptr, b1, P, M, 2048, 128, 1);

    // Layer 2: t2 = h1@W2l -> Q ; aggT2 = meanAgg(t2) -> R ;
    //          h2 = relu(aggT2 + h1@W2r + b2) -> Q
    gemm_tf32_kernel<<<gN2, 256>>>(P, W2l, nullptr, nullptr, nullptr, nullptr, Q, M, 2048, 2048, 0);
    agg_mean_kernel<2048><<<M, 128>>>(Q, rowptr, colsrc, invdeg, R);
    gemm_tf32_kernel<<<gN2, 256>>>(P, W2r, nullptr, nullptr, R, b2, Q, M, 2048, 2048, 1);

    // Layer 3: t3 = h2@W3l -> P ; aggT3 = meanAgg(t3) -> R ;
    //          h3 = relu(aggT3 + h2@W3r + b3) -> d_out
    gemm_tf32_kernel<<<gN1, 256>>>(Q, W3l, nullptr, nullptr, nullptr, nullptr, P, M, 1024, 2048, 0);
    agg_mean_kernel<1024><<<M, 128>>>(P, rowptr, colsrc, invdeg, R);
    gemm_tf32_kernel<<<gN1, 256>>>(Q, W3r, nullptr, nullptr, R, b3, out, M, 1024, 2048, 1);

    // L2 normalize rows (in-place on d_out)
    norm_kernel<<<M, 256>>>(out, out);
}

// round 5
// speedup vs baseline: 1.0015x; 1.0015x over previous
#include <cuda_runtime.h>
#include <cstdint>

// ---------------------------------------------------------------------------
// GraphSAGE 3-layer, tf32 mma.sync GEMMs (cp.async double-buffered, dynamic
// smem) + CSR gather mean-aggregation.
// Identity: meanAgg(H) @ W == meanAgg(H @ W)  (aggregate the narrower one)
// ---------------------------------------------------------------------------

#define N_NODES_MAX 50000
#define N_EDGES_MAX 400000

__device__ float g_P[(size_t)N_NODES_MAX * 2048];
__device__ float g_Q[(size_t)N_NODES_MAX * 2048];
__device__ float g_R[(size_t)N_NODES_MAX * 2048];
__device__ float g_AGGX[(size_t)N_NODES_MAX * 128];
__device__ int   g_cnt[N_NODES_MAX];
__device__ int   g_rowptr[N_NODES_MAX + 1];
__device__ int   g_cursor[N_NODES_MAX];
__device__ int   g_colsrc[N_EDGES_MAX];
__device__ float g_invdeg[N_NODES_MAX];
__device__ int   g_is64;

// ---------------------------------------------------------------------------
// Edge-index dtype autodetect: int64 values < 2^31 have zero high words.
// ---------------------------------------------------------------------------
__global__ void detect_kernel(const int* __restrict__ ei_w) {
    int allz = 1;
    for (int i = 1; i < 512; i += 2)
        if (ei_w[i] != 0) { allz = 0; break; }
    g_is64 = allz;
}

__device__ __forceinline__ int load_idx(const void* ei, size_t pos, int is64) {
    if (is64) return (int)((const long long*)ei)[pos];
    return ((const int*)ei)[pos];
}

// ---------------------------------------------------------------------------
// CSR build
// ---------------------------------------------------------------------------
__global__ void zero_int_kernel(int* p, int n) {
    int i = blockIdx.x * blockDim.x + threadIdx.x;
    if (i < n) p[i] = 0;
}

__global__ void count_kernel(const void* __restrict__ ei, int* __restrict__ cnt,
                             int E, int N) {
    int e = blockIdx.x * blockDim.x + threadIdx.x;
    if (e < E) {
        int d = load_idx(ei, (size_t)E + e, g_is64);
        if (d >= 0 && d < N) atomicAdd(&cnt[d], 1);
    }
}

// single-block exclusive scan, warp-shuffle based
__global__ void scan_kernel(const int* __restrict__ cnt, int* __restrict__ rowptr, int N) {
    __shared__ int warpsum[32];
    __shared__ int s_carry;
    int tid = threadIdx.x, lane = tid & 31, warp = tid >> 5;
    if (tid == 0) s_carry = 0;
    __syncthreads();
    for (int base = 0; base < N; base += 1024) {
        int v = (base + tid < N) ? cnt[base + tid] : 0;
        int s = v;
#pragma unroll
        for (int off = 1; off < 32; off <<= 1) {
            int t = __shfl_up_sync(0xffffffffu, s, off);
            if (lane >= off) s += t;
        }
        if (lane == 31) warpsum[warp] = s;
        __syncthreads();
        if (warp == 0) {
            int w = warpsum[lane];
            int ws = w;
#pragma unroll
            for (int off = 1; off < 32; off <<= 1) {
                int t = __shfl_up_sync(0xffffffffu, ws, off);
                if (lane >= off) ws += t;
            }
            warpsum[lane] = ws - w;  // exclusive
        }
        __syncthreads();
        int excl = s - v + warpsum[warp] + s_carry;
        if (base + tid < N) rowptr[base + tid] = excl;
        __syncthreads();
        if (tid == 1023) s_carry = excl + v;
        __syncthreads();
    }
    if (tid == 0) rowptr[N] = s_carry;
}

__global__ void prep_kernel(const int* __restrict__ cnt, const int* __restrict__ rowptr,
                            float* __restrict__ invdeg, int* __restrict__ cursor, int N) {
    int i = blockIdx.x * blockDim.x + threadIdx.x;
    if (i < N) {
        cursor[i] = rowptr[i];
        int c = cnt[i];
        invdeg[i] = 1.0f / (float)(c > 0 ? c : 1);
    }
}

__global__ void fill_kernel(const void* __restrict__ ei, int* __restrict__ cursor,
                            int* __restrict__ colsrc, int E, int N) {
    int e = blockIdx.x * blockDim.x + threadIdx.x;
    if (e < E) {
        int is64 = g_is64;
        int d = load_idx(ei, (size_t)E + e, is64);
        int s = load_idx(ei, (size_t)e, is64);
        if (d >= 0 && d < N && s >= 0 && s < N) {
            int p = atomicAdd(&cursor[d], 1);
            if (p < E) colsrc[p] = s;
        }
    }
}

// ---------------------------------------------------------------------------
// Mean aggregation
// ---------------------------------------------------------------------------
template <int D>
__global__ void agg_mean_kernel(const float* __restrict__ X,
                                const int* __restrict__ rowptr,
                                const int* __restrict__ colsrc,
                                const float* __restrict__ invdeg,
                                float* __restrict__ out) {
    constexpr int NF4 = D / 4;
    constexpr int TPB = 128;
    constexpr int PT = (NF4 + TPB - 1) / TPB;
    int n = blockIdx.x;
    int tid = threadIdx.x;

    float4 acc[PT];
#pragma unroll
    for (int k = 0; k < PT; k++) acc[k] = make_float4(0.f, 0.f, 0.f, 0.f);

    int s = rowptr[n], e = rowptr[n + 1];
    for (int j = s; j < e; j++) {
        const float4* row = (const float4*)(X + (size_t)colsrc[j] * D);
#pragma unroll
        for (int k = 0; k < PT; k++) {
            int c = tid + k * TPB;
            if (NF4 % TPB == 0 || c < NF4) {
                float4 v = row[c];
                acc[k].x += v.x; acc[k].y += v.y; acc[k].z += v.z; acc[k].w += v.w;
            }
        }
    }
    float sc = invdeg[n];
    float4* orow = (float4*)(out + (size_t)n * D);
#pragma unroll
    for (int k = 0; k < PT; k++) {
        int c = tid + k * TPB;
        if (NF4 % TPB == 0 || c < NF4) {
            float4 a = acc[k];
            a.x *= sc; a.y *= sc; a.z *= sc; a.w *= sc;
            orow[c] = a;
        }
    }
}

// ---------------------------------------------------------------------------
// TF32 GEMM via mma.sync.m16n8k8 (row.col), cp.async double-buffered.
// Dynamic shared memory (71.7 KB > 48 KB static cap).
// Block tile 128x128x32, 256 threads = 8 warps (2x4), warp tile 64x32.
// ---------------------------------------------------------------------------
__device__ __forceinline__ uint32_t f2tf(float x) {
    uint32_t r;
    asm("cvt.rna.tf32.f32 %0, %1;" : "=r"(r) : "f"(x));
    return r;
}

__device__ __forceinline__ void cp_async16(uint32_t dst, const void* src, int src_sz) {
    asm volatile("cp.async.cg.shared.global [%0], [%1], 16, %2;"
                 :: "r"(dst), "l"(src), "r"(src_sz));
}

#define BM 128
#define BN 128
#define BKK 32
#define ASTRIDE 36   // f32 words per A row (pad, row start stays 16B aligned)
#define WSTRIDE 136
#define A_BUF_WORDS (BM * ASTRIDE)       // 4608
#define W_BUF_WORDS (BKK * WSTRIDE)      // 4352
#define GEMM_SMEM_BYTES ((2 * A_BUF_WORDS + 2 * W_BUF_WORDS) * 4)  // 71680

__global__ __launch_bounds__(256) void gemm_tf32_kernel(
    const float* __restrict__ A1, const float* __restrict__ W1,
    const float* __restrict__ A2, const float* __restrict__ W2,
    const float* __restrict__ Cin, const float* __restrict__ bias,
    float* __restrict__ C, int M, int Nout, int K, int do_relu) {
    extern __shared__ float smem[];
    float* As = smem;                       // [2][A_BUF_WORDS]
    float* Ws = smem + 2 * A_BUF_WORDS;     // [2][W_BUF_WORDS]

    int tid = threadIdx.x;
    int bm = blockIdx.y * BM, bn = blockIdx.x * BN;
    int warp = tid >> 5, lane = tid & 31;
    int g = lane >> 2, tg = lane & 3;
    int wm = (warp >> 2) * 64, wn = (warp & 3) * 32;

    uint32_t as_base = (uint32_t)__cvta_generic_to_shared(As);
    uint32_t ws_base = (uint32_t)__cvta_generic_to_shared(Ws);

    float acc[4][4][4];
#pragma unroll
    for (int i = 0; i < 4; i++)
#pragma unroll
        for (int j = 0; j < 4; j++)
#pragma unroll
            for (int k = 0; k < 4; k++) acc[i][j][k] = 0.f;

    int npass = (A2 != nullptr) ? 2 : 1;
    int ntiles = K / BKK;
    int total = npass * ntiles;

    int ar[4], ac4[4], wr[4], wc4[4];
#pragma unroll
    for (int i = 0; i < 4; i++) {
        int idx = tid + i * 256;
        ar[i] = idx >> 3;  ac4[i] = idx & 7;
        wr[i] = idx >> 5;  wc4[i] = idx & 31;
    }

    auto issue = [&](int t, int buf) {
        int pass = t / ntiles;
        int kt = (t % ntiles) * BKK;
        const float* Ap = pass ? A2 : A1;
        const float* Wp = pass ? W2 : W1;
#pragma unroll
        for (int i = 0; i < 4; i++) {
            int gm = bm + ar[i];
            uint32_t d = as_base + (uint32_t)(buf * A_BUF_WORDS + ar[i] * ASTRIDE + ac4[i] * 4) * 4u;
            const float* s = Ap + (size_t)gm * K + kt + ac4[i] * 4;
            cp_async16(d, s, (gm < M) ? 16 : 0);
        }
#pragma unroll
        for (int i = 0; i < 4; i++) {
            uint32_t d = ws_base + (uint32_t)(buf * W_BUF_WORDS + wr[i] * WSTRIDE + wc4[i] * 4) * 4u;
            const float* s = Wp + (size_t)(kt + wr[i]) * Nout + bn + wc4[i] * 4;
            cp_async16(d, s, 16);
        }
        asm volatile("cp.async.commit_group;" ::: "memory");
    };

    issue(0, 0);

    for (int t = 0; t < total; t++) {
        int buf = t & 1;
        asm volatile("cp.async.wait_group 0;" ::: "memory");
        __syncthreads();
        if (t + 1 < total) issue(t + 1, buf ^ 1);

        const float* Asb = &As[buf * A_BUF_WORDS];
        const float* Wsb = &Ws[buf * W_BUF_WORDS];
#pragma unroll
        for (int ks = 0; ks < BKK; ks += 8) {
            uint32_t a[4][4], b[4][2];
#pragma unroll
            for (int im = 0; im < 4; im++) {
                int row = wm + 16 * im + g;
                const float* p = &Asb[row * ASTRIDE + ks];
                a[im][0] = f2tf(p[tg]);
                a[im][1] = f2tf(p[8 * ASTRIDE + tg]);
                a[im][2] = f2tf(p[tg + 4]);
                a[im][3] = f2tf(p[8 * ASTRIDE + tg + 4]);
            }
#pragma unroll
            for (int in = 0; in < 4; in++) {
                int col = wn + 8 * in + g;
                b[in][0] = f2tf(Wsb[(ks + tg) * WSTRIDE + col]);
                b[in][1] = f2tf(Wsb[(ks + tg + 4) * WSTRIDE + col]);
            }
#pragma unroll
            for (int im = 0; im < 4; im++)
#pragma unroll
                for (int in = 0; in < 4; in++) {
                    asm volatile(
                        "mma.sync.aligned.m16n8k8.row.col.f32.tf32.tf32.f32 "
                        "{%0,%1,%2,%3}, {%4,%5,%6,%7}, {%8,%9}, {%0,%1,%2,%3};"
                        : "+f"(acc[im][in][0]), "+f"(acc[im][in][1]),
                          "+f"(acc[im][in][2]), "+f"(acc[im][in][3])
                        : "r"(a[im][0]), "r"(a[im][1]), "r"(a[im][2]), "r"(a[im][3]),
                          "r"(b[in][0]), "r"(b[in][1]));
                }
        }
        // Next iteration's top barrier orders compute(t) before reuse of this buf.
    }

    // epilogue
#pragma unroll
    for (int im = 0; im < 4; im++) {
        int row = wm + 16 * im + g;
#pragma unroll
        for (int half = 0; half < 2; half++) {
            int gm = bm + row + half * 8;
            if (gm >= M) continue;
#pragma unroll
            for (int in = 0; in < 4; in++) {
                int gcol = bn + wn + 8 * in + 2 * tg;
#pragma unroll
                for (int j = 0; j < 2; j++) {
                    float v = acc[im][in][half * 2 + j];
                    size_t idx = (size_t)gm * Nout + gcol + j;
                    if (Cin) v += Cin[idx];
                    if (bias) v += bias[gcol + j];
                    if (do_relu) v = fmaxf(v, 0.f);
                    C[idx] = v;
                }
            }
        }
    }
}

// ---------------------------------------------------------------------------
// Row L2 normalize, D = 1024.
// ---------------------------------------------------------------------------
__global__ void norm_kernel(const float* __restrict__ H, float* __restrict__ out) {
    int n = blockIdx.x, tid = threadIdx.x;
    const float4* row = (const float4*)(H + (size_t)n * 1024);
    float4 v = row[tid];
    float ss = v.x * v.x + v.y * v.y + v.z * v.z + v.w * v.w;
#pragma unroll
    for (int off = 16; off; off >>= 1) ss += __shfl_xor_sync(0xffffffffu, ss, off);
    __shared__ float red[8];
    __shared__ float s_scale;
    int warp = tid >> 5, lane = tid & 31;
    if (lane == 0) red[warp] = ss;
    __syncthreads();
    if (tid == 0) {
        float t = 0.f;
#pragma unroll
        for (int i = 0; i < 8; i++) t += red[i];
        float nm = sqrtf(t);
        s_scale = 1.0f / fmaxf(nm, 1e-12f);
    }
    __syncthreads();
    float sc = s_scale;
    float4* o = (float4*)(out + (size_t)n * 1024);
    v.x *= sc; v.y *= sc; v.z *= sc; v.w *= sc;
    o[tid] = v;
}

// ---------------------------------------------------------------------------
// Launch
// ---------------------------------------------------------------------------
extern "C" void kernel_launch(void* const* d_in, const int* in_sizes, int n_in,
                              void* d_out, int out_size) {
    const float* x       = (const float*)d_in[0];
    const void*  ei      = (const void*)d_in[2];
    const float* W1l     = (const float*)d_in[3];
    const float* W1r     = (const float*)d_in[4];
    const float* b1      = (const float*)d_in[5];
    const float* W2l     = (const float*)d_in[6];
    const float* W2r     = (const float*)d_in[7];
    const float* b2      = (const float*)d_in[8];
    const float* W3l     = (const float*)d_in[9];
    const float* W3r     = (const float*)d_in[10];
    const float* b3      = (const float*)d_in[11];
    float* out           = (float*)d_out;

    int M = in_sizes[0] / 128;
    int E = in_sizes[2] / 2;

    float *P, *Q, *R, *AGGX, *invdeg;
    int *cnt, *rowptr, *cursor, *colsrc;
    cudaGetSymbolAddress((void**)&P, g_P);
    cudaGetSymbolAddress((void**)&Q, g_Q);
    cudaGetSymbolAddress((void**)&R, g_R);
    cudaGetSymbolAddress((void**)&AGGX, g_AGGX);
    cudaGetSymbolAddress((void**)&cnt, g_cnt);
    cudaGetSymbolAddress((void**)&rowptr, g_rowptr);
    cudaGetSymbolAddress((void**)&cursor, g_cursor);
    cudaGetSymbolAddress((void**)&colsrc, g_colsrc);
    cudaGetSymbolAddress((void**)&invdeg, g_invdeg);

    // Opt-in to >48KB dynamic smem (idempotent; non-stream API, capture-safe)
    cudaFuncSetAttribute(gemm_tf32_kernel,
                         cudaFuncAttributeMaxDynamicSharedMemorySize,
                         GEMM_SMEM_BYTES);

    // dtype autodetect + CSR build
    detect_kernel<<<1, 1>>>((const int*)ei);
    zero_int_kernel<<<(M + 255) / 256, 256>>>(cnt, M);
    count_kernel<<<(E + 255) / 256, 256>>>(ei, cnt, E, M);
    scan_kernel<<<1, 1024>>>(cnt, rowptr, M);
    prep_kernel<<<(M + 255) / 256, 256>>>(cnt, rowptr, invdeg, cursor, M);
    fill_kernel<<<(E + 255) / 256, 256>>>(ei, cursor, colsrc, E, M);

    dim3 gN2((2048 / BN), (M + BM - 1) / BM);
    dim3 gN1((1024 / BN), (M + BM - 1) / BM);

    // Layer 1: h1 = relu( meanAgg(x)@W1l + x@W1r + b1 )   -> P
    agg_mean_kernel<128><<<M, 128>>>(x, rowptr, colsrc, invdeg, AGGX);
    gemm_tf32_kernel<<<gN2, 256, GEMM_SMEM_BYTES>>>(AGGX, W1l, x, W1r, nullptr, b1, P, M, 2048, 128, 1);

    // Layer 2: t2 = h1@W2l -> Q ; aggT2 = meanAgg(t2) -> R ;
    //          h2 = relu(aggT2 + h1@W2r + b2) -> Q
    gemm_tf32_kernel<<<gN2, 256, GEMM_SMEM_BYTES>>>(P, W2l, nullptr, nullptr, nullptr, nullptr, Q, M, 2048, 2048, 0);
    agg_mean_kernel<2048><<<M, 128>>>(Q, rowptr, colsrc, invdeg, R);
    gemm_tf32_kernel<<<gN2, 256, GEMM_SMEM_BYTES>>>(P, W2r, nullptr, nullptr, R, b2, Q, M, 2048, 2048, 1);

    // Layer 3: t3 = h2@W3l -> P ; aggT3 = meanAgg(t3) -> R ;
    //          h3 = relu(aggT3 + h2@W3r + b3) -> d_out
    gemm_tf32_kernel<<<gN1, 256, GEMM_SMEM_BYTES>>>(Q, W3l, nullptr, nullptr, nullptr, nullptr, P, M, 1024, 2048, 0);
    agg_mean_kernel<1024><<<M, 128>>>(P, rowptr, colsrc, invdeg, R);
    gemm_tf32_kernel<<<gN1, 256, GEMM_SMEM_BYTES>>>(Q, W3r, nullptr, nullptr, R, b3, out, M, 1024, 2048, 1);

    // L2 normalize rows (in-place on d_out)
    norm_kernel<<<M, 256>>>(out, out);
}